// round 4
// baseline (speedup 1.0000x reference)
#include <cuda_runtime.h>
#include <math.h>
#include <stdint.h>

// Problem constants
#define M_ROWS   16384      // B*S
#define E_DIM    768
#define NQ       8
#define FFN_DIM  3072
#define LN_EPS   1e-5f

// ---------------------------------------------------------------------------
// Scratch (device globals: no cudaMalloc allowed)
// ---------------------------------------------------------------------------
__device__ float g_cx [M_ROWS * E_DIM];     // cos(x + rx), tf32-rounded
__device__ float g_z  [M_ROWS * E_DIM];     // pre-LN1
__device__ float g_x1 [M_ROWS * E_DIM];     // LN1 output (full fp32)
__device__ float g_q  [M_ROWS * NQ];
__device__ float g_h  [M_ROWS * FFN_DIM];   // relu(q@W1+b1), tf32-rounded
__device__ float g_f  [M_ROWS * E_DIM];     // pre-LN2
__device__ float g_WcT[E_DIM * E_DIM];      // Wc^T, tf32-rounded
__device__ float g_W2T[E_DIM * FFN_DIM];    // W2^T, tf32-rounded

// ---------------------------------------------------------------------------
// Helpers (baseline PTX only — harness compiles via compute_103, no 'a' feats)
// ---------------------------------------------------------------------------
__device__ __forceinline__ float to_tf32(float x) {
    uint32_t r;
    asm("cvt.rna.tf32.f32 %0, %1;" : "=r"(r) : "f"(x));
    return __uint_as_float(r);
}

__device__ __forceinline__ void cp16(uint32_t s, const void* g) {
    asm volatile("cp.async.ca.shared.global [%0], [%1], 16;" :: "r"(s), "l"(g));
}
#define CP_COMMIT() asm volatile("cp.async.commit_group;" ::: "memory")
#define CP_WAIT(n)  asm volatile("cp.async.wait_group %0;" :: "n"(n) : "memory")

__device__ __forceinline__ uint32_t smem_u32(const void* p) {
    uint32_t a;
    asm("{ .reg .u64 t; cvta.to.shared.u64 t, %1; cvt.u32.u64 %0, t; }"
        : "=r"(a) : "l"(p));
    return a;
}

__device__ __forceinline__ void mma8(float* c,
                                     uint32_t a0, uint32_t a1, uint32_t a2, uint32_t a3,
                                     uint32_t b0, uint32_t b1) {
    asm volatile(
        "mma.sync.aligned.m16n8k8.row.col.f32.tf32.tf32.f32 "
        "{%0,%1,%2,%3}, {%4,%5,%6,%7}, {%8,%9}, {%0,%1,%2,%3};"
        : "+f"(c[0]), "+f"(c[1]), "+f"(c[2]), "+f"(c[3])
        : "r"(a0), "r"(a1), "r"(a2), "r"(a3), "r"(b0), "r"(b1));
}

// ---------------------------------------------------------------------------
// Tensor-core GEMM (mma.sync tf32):
//   C[M, 768] = A[M, K] @ Bt[768, K]^T + bias + res
// CTA: 256 threads (8 warps), tile 256(M) x 128(N), warp tile 64x64.
// K_TILE=32, cp.async double buffer. Smem rows stride 36 floats (conflict-free).
// ---------------------------------------------------------------------------
#define KT        32
#define TS        36                        // smem row stride (floats)
#define A_FL      (256 * TS)                // A tile floats
#define B_FL      (128 * TS)                // B tile floats
#define STAGE_FL  (A_FL + B_FL)
#define SMEM_FL   (2 * STAGE_FL)
#define SMEM_BYTES (SMEM_FL * 4)            // 110592 B

__global__ void __launch_bounds__(256, 1)
gemm_mma_kernel(const float* __restrict__ A, const float* __restrict__ Bt,
                const float* __restrict__ bias, const float* __restrict__ res,
                float* __restrict__ C, int K, int NK)
{
    extern __shared__ float smem[];
    const uint32_t sbase = smem_u32(smem);

    const int tid  = threadIdx.x;
    const int w    = tid >> 5, lane = tid & 31;
    const int g    = lane >> 2, tg = lane & 3;
    const int row0 = blockIdx.y * 256;
    const int col0 = blockIdx.x * 128;
    const int wm   = (w >> 1) * 64;         // 0,64,128,192
    const int wn   = (w & 1) * 64;          // 0,64

    // copy mapping: 256 threads; rows (tid>>3)+32p, float4 col tid&7
    const int crow = tid >> 3;              // 0..31
    const int ccol = tid & 7;
    const float* Agb = A  + (size_t)(row0 + crow) * K + ccol * 4;
    const float* Bgb = Bt + (size_t)(col0 + crow) * K + ccol * 4;

    float acc[4][8][4];
    #pragma unroll
    for (int i = 0; i < 4; i++)
        #pragma unroll
        for (int j = 0; j < 8; j++)
            #pragma unroll
            for (int v = 0; v < 4; v++) acc[i][j][v] = 0.f;

    auto issue = [&](int kt, int s) {
        const int k0 = kt * KT;
        const uint32_t sA = sbase + (uint32_t)(s * STAGE_FL) * 4u;
        const uint32_t sB = sA + (uint32_t)A_FL * 4u;
        const uint32_t so0 = (uint32_t)(crow * TS + ccol * 4) * 4u;
        #pragma unroll
        for (int p = 0; p < 8; p++)
            cp16(sA + so0 + (uint32_t)(32 * p * TS) * 4u,
                 Agb + (size_t)(32 * p) * K + k0);
        #pragma unroll
        for (int p = 0; p < 4; p++)
            cp16(sB + so0 + (uint32_t)(32 * p * TS) * 4u,
                 Bgb + (size_t)(32 * p) * K + k0);
        CP_COMMIT();
    };

    issue(0, 0);
    if (NK > 1) issue(1, 1);

    for (int kt = 0; kt < NK; kt++) {
        const int s = kt & 1;
        if (kt < NK - 1) { CP_WAIT(1); } else { CP_WAIT(0); }
        __syncthreads();

        const float* As = smem + s * STAGE_FL;
        const float* Bs = As + A_FL;
        const float* Aw = As + (wm + g) * TS + tg;
        const float* Bw = Bs + (wn + g) * TS + tg;

        #pragma unroll
        for (int kk = 0; kk < KT; kk += 8) {
            uint32_t a[4][4];
            #pragma unroll
            for (int i = 0; i < 4; i++) {
                a[i][0] = __float_as_uint(Aw[(16 * i    ) * TS + kk    ]);
                a[i][1] = __float_as_uint(Aw[(16 * i + 8) * TS + kk    ]);
                a[i][2] = __float_as_uint(Aw[(16 * i    ) * TS + kk + 4]);
                a[i][3] = __float_as_uint(Aw[(16 * i + 8) * TS + kk + 4]);
            }
            uint32_t b[8][2];
            #pragma unroll
            for (int j = 0; j < 8; j++) {
                b[j][0] = __float_as_uint(Bw[(8 * j) * TS + kk    ]);
                b[j][1] = __float_as_uint(Bw[(8 * j) * TS + kk + 4]);
            }
            #pragma unroll
            for (int i = 0; i < 4; i++)
                #pragma unroll
                for (int j = 0; j < 8; j++)
                    mma8(acc[i][j], a[i][0], a[i][1], a[i][2], a[i][3],
                         b[j][0], b[j][1]);
        }
        __syncthreads();
        if (kt + 2 < NK) issue(kt + 2, s);
    }

    // Epilogue: + bias + res -> C (float2, cols even)
    float2 bj[8];
    #pragma unroll
    for (int j = 0; j < 8; j++)
        bj[j] = *(const float2*)(bias + col0 + wn + 8 * j + 2 * tg);

    #pragma unroll
    for (int i = 0; i < 4; i++) {
        const int r0 = row0 + wm + 16 * i + g;
        const int r1 = r0 + 8;
        #pragma unroll
        for (int j = 0; j < 8; j++) {
            const int c = col0 + wn + 8 * j + 2 * tg;
            const size_t i0 = (size_t)r0 * E_DIM + c;
            const size_t i1 = (size_t)r1 * E_DIM + c;
            float2 rv0 = *(const float2*)(res + i0);
            float2 rv1 = *(const float2*)(res + i1);
            float2 o0, o1;
            o0.x = acc[i][j][0] + bj[j].x + rv0.x;
            o0.y = acc[i][j][1] + bj[j].y + rv0.y;
            o1.x = acc[i][j][2] + bj[j].x + rv1.x;
            o1.y = acc[i][j][3] + bj[j].y + rv1.y;
            *(float2*)(C + i0) = o0;
            *(float2*)(C + i1) = o1;
        }
    }
}

// ---------------------------------------------------------------------------
// cos(x + rx) precompute, tf32-rounded
// ---------------------------------------------------------------------------
__global__ void __launch_bounds__(256)
cosx_kernel(const float* __restrict__ x, const float* __restrict__ rx,
            float* __restrict__ cx)
{
    const int i = blockIdx.x * 256 + threadIdx.x;       // float4 index
    float4 v = ((const float4*)x)[i];
    const int e = (i * 4) & 63;
    v.x = to_tf32(cosf(v.x + rx[e + 0]));
    v.y = to_tf32(cosf(v.y + rx[e + 1]));
    v.z = to_tf32(cosf(v.z + rx[e + 2]));
    v.w = to_tf32(cosf(v.w + rx[e + 3]));
    ((float4*)cx)[i] = v;
}

// ---------------------------------------------------------------------------
// Transpose: in R x C -> out C x R, tf32-rounded
// ---------------------------------------------------------------------------
__global__ void __launch_bounds__(256)
transpose_kernel(const float* __restrict__ in, float* __restrict__ out, int R, int C)
{
    __shared__ float t[32][33];
    const int c0 = blockIdx.x * 32, r0 = blockIdx.y * 32;
    #pragma unroll
    for (int j = 0; j < 4; j++)
        t[threadIdx.y + j * 8][threadIdx.x] =
            in[(size_t)(r0 + threadIdx.y + j * 8) * C + (c0 + threadIdx.x)];
    __syncthreads();
    #pragma unroll
    for (int j = 0; j < 4; j++)
        out[(size_t)(c0 + threadIdx.y + j * 8) * R + (r0 + threadIdx.x)] =
            to_tf32(t[threadIdx.x][threadIdx.y + j * 8]);
}

// ---------------------------------------------------------------------------
// Row LayerNorm over E=768 (one block per row); optionally writes q
// ---------------------------------------------------------------------------
template <bool WRITE_Q>
__global__ void __launch_bounds__(256)
ln_kernel(const float* __restrict__ in, const float* __restrict__ g,
          const float* __restrict__ b, const float* __restrict__ ry,
          float* __restrict__ out, float* __restrict__ q)
{
    const int m   = blockIdx.x;
    const int tid = threadIdx.x;
    const float* row = in + (size_t)m * E_DIM;

    float v[3];
    float s = 0.f, ss = 0.f;
    #pragma unroll
    for (int j = 0; j < 3; j++) {
        v[j] = row[tid + j * 256];
        s  += v[j];
        ss += v[j] * v[j];
    }
    #pragma unroll
    for (int o = 16; o > 0; o >>= 1) {
        s  += __shfl_xor_sync(0xffffffffu, s,  o);
        ss += __shfl_xor_sync(0xffffffffu, ss, o);
    }
    __shared__ float red[16];
    const int warp = tid >> 5, lane = tid & 31;
    if (lane == 0) { red[warp] = s; red[warp + 8] = ss; }
    __syncthreads();
    if (tid == 0) {
        float S = 0.f, SS = 0.f;
        #pragma unroll
        for (int w = 0; w < 8; w++) { S += red[w]; SS += red[w + 8]; }
        red[0] = S; red[8] = SS;
    }
    __syncthreads();

    const float mu  = red[0] * (1.f / E_DIM);
    const float var = red[8] * (1.f / E_DIM) - mu * mu;
    const float inv = rsqrtf(var + LN_EPS);

    #pragma unroll
    for (int j = 0; j < 3; j++) {
        const int e = tid + j * 256;
        const float y = (v[j] - mu) * inv * g[e] + b[e];
        out[(size_t)m * E_DIM + e] = y;
        if (WRITE_Q && j == 0 && tid < NQ)
            q[(size_t)m * NQ + tid] = cosf(y) * cosf(ry[tid]);
    }
}

// ---------------------------------------------------------------------------
// FFN first layer (tiled): h = relu(q @ W1 + b1), K=8.
// Block: 256 rows x 1024 cols. W1 tile (8x1024) + b1 tile staged in smem once.
// Thread owns 4 cols (float4); loops 256 rows; q row broadcast from smem.
// ---------------------------------------------------------------------------
__global__ void __launch_bounds__(256)
ffn1_kernel(const float* __restrict__ q, const float* __restrict__ W1,
            const float* __restrict__ b1, float* __restrict__ h)
{
    __shared__ float w1s[NQ][1024];
    __shared__ float b1s[1024];
    __shared__ float qs[256][NQ];

    const int col0 = blockIdx.x * 1024;
    const int m0   = blockIdx.y * 256;
    const int tid  = threadIdx.x;

    // stage W1 tile + b1
    #pragma unroll
    for (int i = 0; i < NQ; i++)
        *(float4*)&w1s[i][tid * 4] =
            *(const float4*)(W1 + (size_t)i * FFN_DIM + col0 + tid * 4);
    *(float4*)&b1s[tid * 4] = *(const float4*)(b1 + col0 + tid * 4);
    // stage q tile (256 rows x 8) : 2048 floats, float2 per thread... use 8/thread
    {
        const int r = tid;              // one row per thread
        float2 q01 = *(const float2*)(q + (size_t)(m0 + r) * NQ + 0);
        float2 q23 = *(const float2*)(q + (size_t)(m0 + r) * NQ + 2);
        float2 q45 = *(const float2*)(q + (size_t)(m0 + r) * NQ + 4);
        float2 q67 = *(const float2*)(q + (size_t)(m0 + r) * NQ + 6);
        qs[r][0] = q01.x; qs[r][1] = q01.y;
        qs[r][2] = q23.x; qs[r][3] = q23.y;
        qs[r][4] = q45.x; qs[r][5] = q45.y;
        qs[r][6] = q67.x; qs[r][7] = q67.y;
    }
    __syncthreads();

    // registers: W1 column slice (8 x 4 floats) + bias
    float4 wr[NQ];
    #pragma unroll
    for (int i = 0; i < NQ; i++) wr[i] = *(float4*)&w1s[i][tid * 4];
    const float4 bb = *(float4*)&b1s[tid * 4];

    float* hp = h + (size_t)m0 * FFN_DIM + col0 + tid * 4;
    for (int r = 0; r < 256; r++) {
        float4 acc = bb;
        #pragma unroll
        for (int i = 0; i < NQ; i++) {
            const float qv = qs[r][i];
            acc.x = fmaf(qv, wr[i].x, acc.x);
            acc.y = fmaf(qv, wr[i].y, acc.y);
            acc.z = fmaf(qv, wr[i].z, acc.z);
            acc.w = fmaf(qv, wr[i].w, acc.w);
        }
        acc.x = to_tf32(fmaxf(acc.x, 0.f));
        acc.y = to_tf32(fmaxf(acc.y, 0.f));
        acc.z = to_tf32(fmaxf(acc.z, 0.f));
        acc.w = to_tf32(fmaxf(acc.w, 0.f));
        *(float4*)(hp + (size_t)r * FFN_DIM) = acc;
    }
}

// ---------------------------------------------------------------------------
// Launch
// ---------------------------------------------------------------------------
extern "C" void kernel_launch(void* const* d_in, const int* in_sizes, int n_in,
                              void* d_out, int out_size)
{
    const float* x   = (const float*)d_in[0];
    const float* rx  = (const float*)d_in[1];
    const float* ry  = (const float*)d_in[2];
    const float* Wc  = (const float*)d_in[3];
    const float* bc  = (const float*)d_in[4];
    const float* W1  = (const float*)d_in[5];
    const float* b1  = (const float*)d_in[6];
    const float* W2  = (const float*)d_in[7];
    const float* b2  = (const float*)d_in[8];
    const float* g1  = (const float*)d_in[9];
    const float* be1 = (const float*)d_in[10];
    const float* g2  = (const float*)d_in[11];
    const float* be2 = (const float*)d_in[12];
    float* out = (float*)d_out;

    float *cx, *z, *x1, *q, *h, *f, *WcT, *W2T;
    cudaGetSymbolAddress((void**)&cx,  g_cx);
    cudaGetSymbolAddress((void**)&z,   g_z);
    cudaGetSymbolAddress((void**)&x1,  g_x1);
    cudaGetSymbolAddress((void**)&q,   g_q);
    cudaGetSymbolAddress((void**)&h,   g_h);
    cudaGetSymbolAddress((void**)&f,   g_f);
    cudaGetSymbolAddress((void**)&WcT, g_WcT);
    cudaGetSymbolAddress((void**)&W2T, g_W2T);

    cudaFuncSetAttribute(gemm_mma_kernel,
                         cudaFuncAttributeMaxDynamicSharedMemorySize, SMEM_BYTES);

    // 0) weight transposes (tf32) + cos precompute (tf32)
    transpose_kernel<<<dim3(E_DIM / 32, E_DIM / 32), dim3(32, 8)>>>(Wc, WcT, E_DIM, E_DIM);
    transpose_kernel<<<dim3(E_DIM / 32, FFN_DIM / 32), dim3(32, 8)>>>(W2, W2T, FFN_DIM, E_DIM);
    cosx_kernel<<<(M_ROWS * E_DIM / 4) / 256, 256>>>(x, rx, cx);

    // 1) z = cos(x+rx) @ Wc + bc + x        (tf32 mma.sync)
    gemm_mma_kernel<<<dim3(E_DIM / 128, M_ROWS / 256), 256, SMEM_BYTES>>>(
        cx, WcT, bc, x, z, E_DIM, E_DIM / KT);

    // 2) x1 = LN(z); q = cos(x1[:, :8]) * cos(ry)
    ln_kernel<true><<<M_ROWS, 256>>>(z, g1, be1, ry, x1, q);

    // 3) h = relu(q @ W1 + b1)   (tiled, W1 staged in smem)
    ffn1_kernel<<<dim3(FFN_DIM / 1024, M_ROWS / 256), 256>>>(q, W1, b1, h);

    // 4) f = h @ W2 + b2 + x1               (tf32 mma.sync)
    gemm_mma_kernel<<<dim3(E_DIM / 128, M_ROWS / 256), 256, SMEM_BYTES>>>(
        h, W2T, b2, x1, f, FFN_DIM, FFN_DIM / KT);

    // 5) out = LN(f)
    ln_kernel<false><<<M_ROWS, 256>>>(f, g2, be2, nullptr, out, nullptr);
}

// round 5
// speedup vs baseline: 1.6475x; 1.6475x over previous
#include <cuda_runtime.h>
#include <cuda_fp16.h>
#include <math.h>
#include <stdint.h>

// Problem constants
#define M_ROWS   16384      // B*S
#define E_DIM    768
#define NQ       8
#define FFN_DIM  3072
#define LN_EPS   1e-5f

// ---------------------------------------------------------------------------
// Scratch (device globals: no cudaMalloc allowed)
// ---------------------------------------------------------------------------
__device__ __half g_cx [M_ROWS * E_DIM];    // cos(x + rx), fp16
__device__ float  g_z  [M_ROWS * E_DIM];    // pre-LN1
__device__ float  g_x1 [M_ROWS * E_DIM];    // LN1 output
__device__ float  g_q  [M_ROWS * NQ];
__device__ __half g_h  [M_ROWS * FFN_DIM];  // relu(q@W1+b1), fp16
__device__ float  g_f  [M_ROWS * E_DIM];    // pre-LN2
__device__ __half g_WcT[E_DIM * E_DIM];     // Wc^T, fp16
__device__ __half g_W2T[E_DIM * FFN_DIM];   // W2^T, fp16

// ---------------------------------------------------------------------------
// Helpers (baseline PTX only — compute_103 has no 'a' features)
// ---------------------------------------------------------------------------
__device__ __forceinline__ uint32_t smem_u32(const void* p) {
    uint32_t a;
    asm("{ .reg .u64 t; cvta.to.shared.u64 t, %1; cvt.u32.u64 %0, t; }"
        : "=r"(a) : "l"(p));
    return a;
}

__device__ __forceinline__ void cp16(uint32_t s, const void* g) {
    asm volatile("cp.async.ca.shared.global [%0], [%1], 16;" :: "r"(s), "l"(g));
}
#define CP_COMMIT() asm volatile("cp.async.commit_group;" ::: "memory")
#define CP_WAIT(n)  asm volatile("cp.async.wait_group %0;" :: "n"(n) : "memory")

__device__ __forceinline__ void ldsm4(uint32_t* r, uint32_t addr) {
    asm volatile("ldmatrix.sync.aligned.m8n8.x4.shared.b16 {%0,%1,%2,%3}, [%4];"
        : "=r"(r[0]), "=r"(r[1]), "=r"(r[2]), "=r"(r[3]) : "r"(addr));
}

__device__ __forceinline__ void mma16816(float* c, const uint32_t* a,
                                         uint32_t b0, uint32_t b1) {
    asm volatile(
        "mma.sync.aligned.m16n8k16.row.col.f32.f16.f16.f32 "
        "{%0,%1,%2,%3}, {%4,%5,%6,%7}, {%8,%9}, {%0,%1,%2,%3};"
        : "+f"(c[0]), "+f"(c[1]), "+f"(c[2]), "+f"(c[3])
        : "r"(a[0]), "r"(a[1]), "r"(a[2]), "r"(a[3]), "r"(b0), "r"(b1));
}

// ---------------------------------------------------------------------------
// fp16 tensor-core GEMM:
//   C[M, 768] = A[M, K] @ Bt[768, K]^T + bias + res     (A, Bt fp16; rest fp32)
// CTA: 256 threads (8 warps), tile 256(M) x 128(N), warp tile 64x64.
// K_TILE=64, cp.async double buffer.
// Smem rows: 64 halves payload, 144 B stride (72 halves) -> conflict-free ldmatrix.
// ---------------------------------------------------------------------------
#define KT        64
#define ROW_B     144                       // smem row stride bytes
#define A_BYTES   (256 * ROW_B)
#define B_BYTES   (128 * ROW_B)
#define STAGE_BYTES (A_BYTES + B_BYTES)
#define SMEM_BYTES  (2 * STAGE_BYTES)       // 110592

__global__ void __launch_bounds__(256, 1)
gemm_mma_kernel(const __half* __restrict__ A, const __half* __restrict__ Bt,
                const float* __restrict__ bias, const float* __restrict__ res,
                float* __restrict__ C, int K, int NK)
{
    extern __shared__ char smem[];
    const uint32_t sbase = smem_u32(smem);

    const int tid  = threadIdx.x;
    const int w    = tid >> 5, lane = tid & 31;
    const int g    = lane >> 2, tg = lane & 3;
    const int row0 = blockIdx.y * 256;
    const int col0 = blockIdx.x * 128;
    const int wm   = (w >> 1) * 64;         // 0,64,128,192
    const int wn   = (w & 1) * 64;          // 0,64

    // ldmatrix lane addressing: lanes 0-15 -> rows, lanes 16-31 -> +16B chunk
    const int lrow = lane & 15;
    const int lsel = lane >> 4;

    // cp.async loader mapping: thread -> (row tid>>3, 16B-chunk tid&7)
    const int crow = tid >> 3;              // 0..31
    const int cchk = tid & 7;
    const __half* Ag = A  + (size_t)(row0 + crow) * K + cchk * 8;
    const __half* Bg = Bt + (size_t)(col0 + crow) * K + cchk * 8;

    float acc[4][8][4];
    #pragma unroll
    for (int i = 0; i < 4; i++)
        #pragma unroll
        for (int j = 0; j < 8; j++)
            #pragma unroll
            for (int v = 0; v < 4; v++) acc[i][j][v] = 0.f;

    auto issue = [&](int kt, int s) {
        const int k0 = kt * KT;
        const uint32_t sA = sbase + (uint32_t)s * STAGE_BYTES;
        const uint32_t sB = sA + A_BYTES;
        const uint32_t so = (uint32_t)crow * ROW_B + (uint32_t)cchk * 16u;
        #pragma unroll
        for (int p = 0; p < 8; p++)
            cp16(sA + so + (uint32_t)(32 * p) * ROW_B,
                 Ag + (size_t)(32 * p) * K + k0);
        #pragma unroll
        for (int p = 0; p < 4; p++)
            cp16(sB + so + (uint32_t)(32 * p) * ROW_B,
                 Bg + (size_t)(32 * p) * K + k0);
        CP_COMMIT();
    };

    issue(0, 0);
    if (NK > 1) issue(1, 1);

    for (int kt = 0; kt < NK; kt++) {
        const int s = kt & 1;
        if (kt < NK - 1) { CP_WAIT(1); } else { CP_WAIT(0); }
        __syncthreads();

        const uint32_t sA = sbase + (uint32_t)s * STAGE_BYTES;
        const uint32_t sB = sA + A_BYTES;
        const uint32_t aB = sA + (uint32_t)(wm + lrow) * ROW_B + (uint32_t)lsel * 16u;
        const uint32_t bB = sB + (uint32_t)(wn + lrow) * ROW_B + (uint32_t)lsel * 16u;

        #pragma unroll
        for (int t2 = 0; t2 < 4; t2++) {           // 4 x k16 per stage
            uint32_t a[4][4];
            #pragma unroll
            for (int i = 0; i < 4; i++)
                ldsm4(a[i], aB + (uint32_t)(16 * i) * ROW_B + (uint32_t)t2 * 32u);
            uint32_t b[4][4];
            #pragma unroll
            for (int jj = 0; jj < 4; jj++)
                ldsm4(b[jj], bB + (uint32_t)(16 * jj) * ROW_B + (uint32_t)t2 * 32u);

            #pragma unroll
            for (int i = 0; i < 4; i++)
                #pragma unroll
                for (int j = 0; j < 8; j++) {
                    const int jj = j >> 1, odd = j & 1;
                    mma16816(acc[i][j], a[i], b[jj][odd], b[jj][2 + odd]);
                }
        }
        __syncthreads();
        if (kt + 2 < NK) issue(kt + 2, s);
    }

    // Epilogue: + bias + res -> C (float2, cols even)
    float2 bj[8];
    #pragma unroll
    for (int j = 0; j < 8; j++)
        bj[j] = *(const float2*)(bias + col0 + wn + 8 * j + 2 * tg);

    #pragma unroll
    for (int i = 0; i < 4; i++) {
        const int r0 = row0 + wm + 16 * i + g;
        const int r1 = r0 + 8;
        #pragma unroll
        for (int j = 0; j < 8; j++) {
            const int c = col0 + wn + 8 * j + 2 * tg;
            const size_t i0 = (size_t)r0 * E_DIM + c;
            const size_t i1 = (size_t)r1 * E_DIM + c;
            float2 rv0 = *(const float2*)(res + i0);
            float2 rv1 = *(const float2*)(res + i1);
            float2 o0, o1;
            o0.x = acc[i][j][0] + bj[j].x + rv0.x;
            o0.y = acc[i][j][1] + bj[j].y + rv0.y;
            o1.x = acc[i][j][2] + bj[j].x + rv1.x;
            o1.y = acc[i][j][3] + bj[j].y + rv1.y;
            *(float2*)(C + i0) = o0;
            *(float2*)(C + i1) = o1;
        }
    }
}

// ---------------------------------------------------------------------------
// cos(x + rx) precompute -> fp16 (8 elems/thread, 16B store)
// ---------------------------------------------------------------------------
__global__ void __launch_bounds__(256)
cosx_kernel(const float* __restrict__ x, const float* __restrict__ rx,
            __half* __restrict__ cx)
{
    const int i = blockIdx.x * 256 + threadIdx.x;       // 8-elem index
    float4 v0 = ((const float4*)x)[2 * i];
    float4 v1 = ((const float4*)x)[2 * i + 1];
    const int e = (i * 8) & 63;
    __half2 h[4];
    h[0] = __floats2half2_rn(cosf(v0.x + rx[e + 0]), cosf(v0.y + rx[e + 1]));
    h[1] = __floats2half2_rn(cosf(v0.z + rx[e + 2]), cosf(v0.w + rx[e + 3]));
    h[2] = __floats2half2_rn(cosf(v1.x + rx[e + 4]), cosf(v1.y + rx[e + 5]));
    h[3] = __floats2half2_rn(cosf(v1.z + rx[e + 6]), cosf(v1.w + rx[e + 7]));
    ((uint4*)cx)[i] = *(const uint4*)h;
}

// ---------------------------------------------------------------------------
// Transpose: in R x C (fp32) -> out C x R (fp16)
// ---------------------------------------------------------------------------
__global__ void __launch_bounds__(256)
transpose_kernel(const float* __restrict__ in, __half* __restrict__ out, int R, int C)
{
    __shared__ float t[32][33];
    const int c0 = blockIdx.x * 32, r0 = blockIdx.y * 32;
    #pragma unroll
    for (int j = 0; j < 4; j++)
        t[threadIdx.y + j * 8][threadIdx.x] =
            in[(size_t)(r0 + threadIdx.y + j * 8) * C + (c0 + threadIdx.x)];
    __syncthreads();
    #pragma unroll
    for (int j = 0; j < 4; j++)
        out[(size_t)(c0 + threadIdx.y + j * 8) * R + (r0 + threadIdx.x)] =
            __float2half_rn(t[threadIdx.x][threadIdx.y + j * 8]);
}

// ---------------------------------------------------------------------------
// Row LayerNorm over E=768 (one block per row); optionally writes q
// ---------------------------------------------------------------------------
template <bool WRITE_Q>
__global__ void __launch_bounds__(256)
ln_kernel(const float* __restrict__ in, const float* __restrict__ g,
          const float* __restrict__ b, const float* __restrict__ ry,
          float* __restrict__ out, float* __restrict__ q)
{
    const int m   = blockIdx.x;
    const int tid = threadIdx.x;
    const float* row = in + (size_t)m * E_DIM;

    float v[3];
    float s = 0.f, ss = 0.f;
    #pragma unroll
    for (int j = 0; j < 3; j++) {
        v[j] = row[tid + j * 256];
        s  += v[j];
        ss += v[j] * v[j];
    }
    #pragma unroll
    for (int o = 16; o > 0; o >>= 1) {
        s  += __shfl_xor_sync(0xffffffffu, s,  o);
        ss += __shfl_xor_sync(0xffffffffu, ss, o);
    }
    __shared__ float red[16];
    const int warp = tid >> 5, lane = tid & 31;
    if (lane == 0) { red[warp] = s; red[warp + 8] = ss; }
    __syncthreads();
    if (tid == 0) {
        float S = 0.f, SS = 0.f;
        #pragma unroll
        for (int w = 0; w < 8; w++) { S += red[w]; SS += red[w + 8]; }
        red[0] = S; red[8] = SS;
    }
    __syncthreads();

    const float mu  = red[0] * (1.f / E_DIM);
    const float var = red[8] * (1.f / E_DIM) - mu * mu;
    const float inv = rsqrtf(var + LN_EPS);

    #pragma unroll
    for (int j = 0; j < 3; j++) {
        const int e = tid + j * 256;
        const float y = (v[j] - mu) * inv * g[e] + b[e];
        out[(size_t)m * E_DIM + e] = y;
        if (WRITE_Q && j == 0 && tid < NQ)
            q[(size_t)m * NQ + tid] = cosf(y) * cosf(ry[tid]);
    }
}

// ---------------------------------------------------------------------------
// FFN first layer (tiled): h = relu(q @ W1 + b1) -> fp16.
// Block: 256 rows x 1024 cols. W1 tile + b1 staged in smem once.
// ---------------------------------------------------------------------------
__global__ void __launch_bounds__(256)
ffn1_kernel(const float* __restrict__ q, const float* __restrict__ W1,
            const float* __restrict__ b1, __half* __restrict__ h)
{
    __shared__ float w1s[NQ][1024];
    __shared__ float b1s[1024];
    __shared__ float qs[256][NQ];

    const int col0 = blockIdx.x * 1024;
    const int m0   = blockIdx.y * 256;
    const int tid  = threadIdx.x;

    #pragma unroll
    for (int i = 0; i < NQ; i++)
        *(float4*)&w1s[i][tid * 4] =
            *(const float4*)(W1 + (size_t)i * FFN_DIM + col0 + tid * 4);
    *(float4*)&b1s[tid * 4] = *(const float4*)(b1 + col0 + tid * 4);
    {
        const int r = tid;
        float2 q01 = *(const float2*)(q + (size_t)(m0 + r) * NQ + 0);
        float2 q23 = *(const float2*)(q + (size_t)(m0 + r) * NQ + 2);
        float2 q45 = *(const float2*)(q + (size_t)(m0 + r) * NQ + 4);
        float2 q67 = *(const float2*)(q + (size_t)(m0 + r) * NQ + 6);
        qs[r][0] = q01.x; qs[r][1] = q01.y;
        qs[r][2] = q23.x; qs[r][3] = q23.y;
        qs[r][4] = q45.x; qs[r][5] = q45.y;
        qs[r][6] = q67.x; qs[r][7] = q67.y;
    }
    __syncthreads();

    float4 wr[NQ];
    #pragma unroll
    for (int i = 0; i < NQ; i++) wr[i] = *(float4*)&w1s[i][tid * 4];
    const float4 bb = *(float4*)&b1s[tid * 4];

    __half* hp = h + (size_t)m0 * FFN_DIM + col0 + tid * 4;
    for (int r = 0; r < 256; r++) {
        float4 acc = bb;
        #pragma unroll
        for (int i = 0; i < NQ; i++) {
            const float qv = qs[r][i];
            acc.x = fmaf(qv, wr[i].x, acc.x);
            acc.y = fmaf(qv, wr[i].y, acc.y);
            acc.z = fmaf(qv, wr[i].z, acc.z);
            acc.w = fmaf(qv, wr[i].w, acc.w);
        }
        __half2 p0 = __floats2half2_rn(fmaxf(acc.x, 0.f), fmaxf(acc.y, 0.f));
        __half2 p1 = __floats2half2_rn(fmaxf(acc.z, 0.f), fmaxf(acc.w, 0.f));
        uint2 pk = make_uint2(*(uint32_t*)&p0, *(uint32_t*)&p1);
        *(uint2*)(hp + (size_t)r * FFN_DIM) = pk;
    }
}

// ---------------------------------------------------------------------------
// Launch
// ---------------------------------------------------------------------------
extern "C" void kernel_launch(void* const* d_in, const int* in_sizes, int n_in,
                              void* d_out, int out_size)
{
    const float* x   = (const float*)d_in[0];
    const float* rx  = (const float*)d_in[1];
    const float* ry  = (const float*)d_in[2];
    const float* Wc  = (const float*)d_in[3];
    const float* bc  = (const float*)d_in[4];
    const float* W1  = (const float*)d_in[5];
    const float* b1  = (const float*)d_in[6];
    const float* W2  = (const float*)d_in[7];
    const float* b2  = (const float*)d_in[8];
    const float* g1  = (const float*)d_in[9];
    const float* be1 = (const float*)d_in[10];
    const float* g2  = (const float*)d_in[11];
    const float* be2 = (const float*)d_in[12];
    float* out = (float*)d_out;

    __half *cx, *h, *WcT, *W2T;
    float *z, *x1, *q, *f;
    cudaGetSymbolAddress((void**)&cx,  g_cx);
    cudaGetSymbolAddress((void**)&z,   g_z);
    cudaGetSymbolAddress((void**)&x1,  g_x1);
    cudaGetSymbolAddress((void**)&q,   g_q);
    cudaGetSymbolAddress((void**)&h,   g_h);
    cudaGetSymbolAddress((void**)&f,   g_f);
    cudaGetSymbolAddress((void**)&WcT, g_WcT);
    cudaGetSymbolAddress((void**)&W2T, g_W2T);

    cudaFuncSetAttribute(gemm_mma_kernel,
                         cudaFuncAttributeMaxDynamicSharedMemorySize, SMEM_BYTES);

    // 0) weight transposes (fp16) + cos precompute (fp16)
    transpose_kernel<<<dim3(E_DIM / 32, E_DIM / 32), dim3(32, 8)>>>(Wc, WcT, E_DIM, E_DIM);
    transpose_kernel<<<dim3(E_DIM / 32, FFN_DIM / 32), dim3(32, 8)>>>(W2, W2T, FFN_DIM, E_DIM);
    cosx_kernel<<<(M_ROWS * E_DIM / 8) / 256, 256>>>(x, rx, cx);

    // 1) z = cos(x+rx) @ Wc + bc + x        (fp16 mma + ldmatrix)
    gemm_mma_kernel<<<dim3(E_DIM / 128, M_ROWS / 256), 256, SMEM_BYTES>>>(
        cx, WcT, bc, x, z, E_DIM, E_DIM / KT);

    // 2) x1 = LN(z); q = cos(x1[:, :8]) * cos(ry)
    ln_kernel<true><<<M_ROWS, 256>>>(z, g1, be1, ry, x1, q);

    // 3) h = relu(q @ W1 + b1)  -> fp16
    ffn1_kernel<<<dim3(FFN_DIM / 1024, M_ROWS / 256), 256>>>(q, W1, b1, h);

    // 4) f = h @ W2 + b2 + x1               (fp16 mma + ldmatrix)
    gemm_mma_kernel<<<dim3(E_DIM / 128, M_ROWS / 256), 256, SMEM_BYTES>>>(
        h, W2T, b2, x1, f, FFN_DIM, FFN_DIM / KT);

    // 5) out = LN(f)
    ln_kernel<false><<<M_ROWS, 256>>>(f, g2, be2, nullptr, out, nullptr);
}